// round 4
// baseline (speedup 1.0000x reference)
#include <cuda_runtime.h>
#include <cuda_bf16.h>
#include <math.h>
#include <stdint.h>

// ---------------- problem constants ----------------
#define TT 256
#define BBATCH 64
#define HH 512
#define RRD 4
#define WWD 32
#define NND 64
#define HC 759          // HID_C
#define G4C 3036        // 4*HID_C
#define G4E 2048        // 4*H
#define KCC 887         // HC + R*W
#define EPSF 1e-6f

// ---------------- device scratch (no allocs allowed) ----------------
__device__ float g_XWe[(size_t)TT * BBATCH * G4E];   // x @ Wih_e^T + b_e     (134 MB)
__device__ float g_EWc[(size_t)TT * BBATCH * G4C];   // enc @ Wih_c[:, :H]^T + b_c (199 MB)
__device__ float g_enc[(size_t)TT * BBATCH * HH];    // encoder outputs
__device__ float g_he[2][BBATCH * HH];
__device__ float g_ce[BBATCH * HH];
__device__ float g_hc[2][BBATCH * HC];
__device__ float g_cc[BBATCH * HC];
__device__ float g_M[BBATCH * NND * WWD];
__device__ float g_u[BBATCH * NND];
__device__ float g_p[BBATCH * NND];
__device__ float g_ww[BBATCH * NND];
__device__ float g_L[BBATCH * NND * NND];
__device__ float g_wr[BBATCH * RRD * NND];
__device__ float g_rv[BBATCH * RRD * WWD];

__device__ __forceinline__ float sigmf_(float x) { return 1.f / (1.f + expf(-x)); }
__device__ __forceinline__ float softplusf_(float x) { return fmaxf(x, 0.f) + log1pf(expf(-fabsf(x))); }

// ---------------- init: zero all recurrent state ----------------
__global__ void init_states() {
    int i = blockIdx.x * blockDim.x + threadIdx.x;
    if (i < 2 * BBATCH * HH) ((float*)g_he)[i] = 0.f;
    if (i < BBATCH * HH)     g_ce[i] = 0.f;
    if (i < 2 * BBATCH * HC) ((float*)g_hc)[i] = 0.f;
    if (i < BBATCH * HC)     g_cc[i] = 0.f;
    if (i < BBATCH * NND * WWD) g_M[i] = 0.f;
    if (i < BBATCH * NND) { g_u[i] = 0.f; g_p[i] = 0.f; g_ww[i] = 0.f; }
    if (i < BBATCH * NND * NND) g_L[i] = 0.f;
    if (i < BBATCH * RRD * NND) g_wr[i] = 0.f;
    if (i < BBATCH * RRD * WWD) g_rv[i] = 0.f;
}

// ---------------- big input-projection GEMMs ----------------
// phase 0: C[m, n] = x[(b,t), :] @ Wih_e[n, :] + b_e[n]     m = t*64+b, N=2048, ldw=512
// phase 1: C[m, n] = enc[m, :]   @ Wih_c[n, :512] + b_c[n]  N=3036, ldw=640
__global__ __launch_bounds__(256) void gemm_phase(const float* __restrict__ Ain,
                                                  const float* __restrict__ Wt,
                                                  const float* __restrict__ bias,
                                                  int phase) {
    const int Ncols = phase ? G4C : G4E;
    const int ldw   = phase ? 640 : 512;
    float* C        = phase ? g_EWc : g_XWe;
    const float* A  = phase ? g_enc : Ain;

    __shared__ float As[16][65];
    __shared__ float Bs[16][65];

    int tid = threadIdx.x;
    int m0 = blockIdx.x * 64;
    int n0 = blockIdx.y * 64;
    int tn = tid & 15, tm = tid >> 4;

    float acc[4][4];
#pragma unroll
    for (int i = 0; i < 4; i++)
#pragma unroll
        for (int j = 0; j < 4; j++) acc[i][j] = 0.f;

    for (int k0 = 0; k0 < 512; k0 += 16) {
#pragma unroll
        for (int i = 0; i < 4; i++) {
            int idx = tid + 256 * i;          // 0..1023
            int mm = idx >> 4, kk = idx & 15;
            int m = m0 + mm;
            const float* arow;
            if (phase) arow = A + (size_t)m * 512;
            else { int t = m >> 6, b = m & 63; arow = A + ((size_t)b * TT + t) * 512; }
            As[kk][mm] = arow[k0 + kk];
        }
#pragma unroll
        for (int i = 0; i < 4; i++) {
            int idx = tid + 256 * i;
            int nn = idx >> 4, kk = idx & 15;
            int n = n0 + nn;
            Bs[kk][nn] = (n < Ncols) ? Wt[(size_t)n * ldw + k0 + kk] : 0.f;
        }
        __syncthreads();
#pragma unroll
        for (int k = 0; k < 16; k++) {
            float a[4], bv[4];
#pragma unroll
            for (int i = 0; i < 4; i++) { a[i] = As[k][tm * 4 + i]; bv[i] = Bs[k][tn * 4 + i]; }
#pragma unroll
            for (int i = 0; i < 4; i++)
#pragma unroll
                for (int j = 0; j < 4; j++) acc[i][j] += a[i] * bv[j];
        }
        __syncthreads();
    }
#pragma unroll
    for (int i = 0; i < 4; i++) {
        int m = m0 + tm * 4 + i;
#pragma unroll
        for (int j = 0; j < 4; j++) {
            int n = n0 + tn * 4 + j;
            if (n < Ncols) C[(size_t)m * Ncols + n] = acc[i][j] + bias[n];
        }
    }
}

// ---------------- encoder step: g = XWe[t] + h@Whh_e^T ; LSTM cell ----------------
// grid 128 blocks (j-chunk of 4), 256 threads. Block owns all 4 gates for its j's.
__global__ __launch_bounds__(256) void enc_step(const float* __restrict__ Whh_e, int t) {
    __shared__ float hs[32][65];
    __shared__ float Ws[16][32];
    __shared__ float gs[16][65];

    int tid = threadIdx.x;
    int j0 = blockIdx.x * 4;
    int par = t & 1;
    const float* hin = g_he[par];
    float* hout = g_he[par ^ 1];

    int bb = tid & 31;
    int ry = tid >> 5;        // 0..7
    int lr0 = ry * 2;         // rows lr0, lr0+1 of 16

    float acc[2][2];
#pragma unroll
    for (int i = 0; i < 2; i++)
#pragma unroll
        for (int r = 0; r < 2; r++) {
            int lr = lr0 + r;
            int gate = lr >> 2, jj = lr & 3;
            int bidx = bb + i * 32;
            acc[i][r] = g_XWe[((size_t)t * BBATCH + bidx) * G4E + gate * HH + j0 + jj];
        }

    for (int k0 = 0; k0 < HH; k0 += 32) {
#pragma unroll
        for (int i = 0; i < 8; i++) {
            int idx = tid + 256 * i;          // 0..2047
            int bl = idx >> 5, kk = idx & 31;
            hs[kk][bl] = hin[bl * HH + k0 + kk];
        }
#pragma unroll
        for (int i = 0; i < 2; i++) {
            int idx = tid + 256 * i;          // 0..511
            int lr = idx >> 5, kk = idx & 31;
            int gate = lr >> 2, jj = lr & 3;
            Ws[lr][kk] = Whh_e[(size_t)(gate * HH + j0 + jj) * HH + k0 + kk];
        }
        __syncthreads();
#pragma unroll
        for (int k = 0; k < 32; k++) {
            float h0 = hs[k][bb], h1 = hs[k][bb + 32];
            float w0 = Ws[lr0][k], w1 = Ws[lr0 + 1][k];
            acc[0][0] += h0 * w0; acc[0][1] += h0 * w1;
            acc[1][0] += h1 * w0; acc[1][1] += h1 * w1;
        }
        __syncthreads();
    }
#pragma unroll
    for (int i = 0; i < 2; i++)
#pragma unroll
        for (int r = 0; r < 2; r++) gs[lr0 + r][bb + 32 * i] = acc[i][r];
    __syncthreads();

    // elementwise LSTM: 64 b x 4 j = 256 elems, one per thread
    int bidx = tid & 63, jj = tid >> 6;
    int j = j0 + jj;
    float gi = gs[jj][bidx], gf = gs[4 + jj][bidx], gg = gs[8 + jj][bidx], go = gs[12 + jj][bidx];
    float c = g_ce[bidx * HH + j];
    float cn = sigmf_(gf) * c + sigmf_(gi) * tanhf(gg);
    float hn = sigmf_(go) * tanhf(cn);
    g_ce[bidx * HH + j] = cn;
    hout[bidx * HH + j] = hn;
    g_enc[((size_t)t * BBATCH + bidx) * HH + j] = hn;
}

// ---------------- controller step: g = EWc[t] + h@Whh_c^T + rv@Wr^T ; LSTM ----------------
// grid 127 blocks (j-chunk of 6), 256 threads.
__global__ __launch_bounds__(256) void ctrl_step(const float* __restrict__ Whh_c,
                                                 const float* __restrict__ Wih_c,
                                                 float* __restrict__ out, int t) {
    __shared__ float hs[32][65];
    __shared__ float Ws[24][32];
    __shared__ float gs[24][65];

    int tid = threadIdx.x;
    int j0 = blockIdx.x * 6;
    int par = t & 1;
    const float* hin = g_hc[par];
    float* hout = g_hc[par ^ 1];

    int bb = tid & 31;
    int ry = tid >> 5;        // 0..7
    int lr0 = ry * 3;         // rows lr0..lr0+2 of 24

    float acc[2][3];
#pragma unroll
    for (int i = 0; i < 2; i++)
#pragma unroll
        for (int r = 0; r < 3; r++) {
            int lr = lr0 + r;
            int gate = lr / 6, jj = lr % 6;
            int j = j0 + jj;
            int bidx = bb + i * 32;
            acc[i][r] = (j < HC) ? g_EWc[((size_t)t * BBATCH + bidx) * G4C + gate * HC + j] : 0.f;
        }

    for (int k0 = 0; k0 < KCC; k0 += 32) {
#pragma unroll
        for (int i = 0; i < 8; i++) {
            int idx = tid + 256 * i;          // 0..2047
            int bl = idx >> 5, kk = idx & 31;
            int k = k0 + kk;
            float v = 0.f;
            if (k < HC) v = hin[bl * HC + k];
            else if (k < KCC) v = g_rv[bl * (RRD * WWD) + (k - HC)];
            hs[kk][bl] = v;
        }
#pragma unroll
        for (int i = 0; i < 3; i++) {
            int idx = tid + 256 * i;          // 0..767
            int lr = idx >> 5, kk = idx & 31;
            int gate = lr / 6, jj = lr % 6;
            int j = j0 + jj;
            int k = k0 + kk;
            float v = 0.f;
            if (j < HC && k < KCC) {
                int grow = gate * HC + j;
                v = (k < HC) ? Whh_c[(size_t)grow * HC + k]
                             : Wih_c[(size_t)grow * 640 + 512 + (k - HC)];
            }
            Ws[lr][kk] = v;
        }
        __syncthreads();
#pragma unroll
        for (int k = 0; k < 32; k++) {
            float h0 = hs[k][bb], h1 = hs[k][bb + 32];
#pragma unroll
            for (int r = 0; r < 3; r++) {
                float w = Ws[lr0 + r][k];
                acc[0][r] += h0 * w;
                acc[1][r] += h1 * w;
            }
        }
        __syncthreads();
    }
#pragma unroll
    for (int i = 0; i < 2; i++)
#pragma unroll
        for (int r = 0; r < 3; r++) gs[lr0 + r][bb + 32 * i] = acc[i][r];
    __syncthreads();

    // elementwise: 64 b x 6 j = 384 elems
    for (int e = tid; e < 64 * 6; e += 256) {
        int bidx = e & 63, jj = e >> 6;
        int j = j0 + jj;
        if (j < HC) {
            float gi = gs[jj][bidx], gf = gs[6 + jj][bidx];
            float gg = gs[12 + jj][bidx], go = gs[18 + jj][bidx];
            float c = g_cc[bidx * HC + j];
            float cn = sigmf_(gf) * c + sigmf_(gi) * tanhf(gg);
            float hn = sigmf_(go) * tanhf(cn);
            g_cc[bidx * HC + j] = cn;
            hout[bidx * HC + j] = hn;
            if (j < HH) out[((size_t)bidx * TT + t) * HH + j] = hn;   // (B,T,H)
        }
    }
}

// ---------------- DNC memory step: one block per batch ----------------
__global__ __launch_bounds__(256) void dnc_step(int t) {
    int b = blockIdx.x;
    int tid = threadIdx.x;
    int par = t & 1;
    const float* h = g_hc[par ^ 1] + b * HC;   // NEW h from ctrl_step of this t

    __shared__ float Ls[64][65];
    __shared__ float Ms[64][33];
    __shared__ float xi[247];
    __shared__ float wrs[4][64];
    __shared__ float wrtmp[4][64];
    __shared__ float us[64], ps[64], wws[64], avec[64], cw[64], wwn[64], su[64], rnorm[64];
    __shared__ int   sidx[64];
    __shared__ float rkn[4][32];
    __shared__ float wkn[32];
    __shared__ float modes[4][3];
    __shared__ float red[64];
    __shared__ float knorm[5];
    __shared__ float sww_sh;

    // -------- loads --------
    for (int i = tid; i < 4096; i += 256) Ls[i >> 6][i & 63] = g_L[b * 4096 + i];
    for (int i = tid; i < 2048; i += 256) Ms[i >> 5][i & 31] = g_M[b * 2048 + i];
    wrs[tid >> 6][tid & 63] = g_wr[b * 256 + tid];
    if (tid < 64) { us[tid] = g_u[b * 64 + tid]; ps[tid] = g_p[b * 64 + tid]; wws[tid] = g_ww[b * 64 + tid]; }
    if (tid < 247) {
        float v = h[HH + tid];
        float a;
        if (tid < 128)      a = tanhf(v);        // read keys
        else if (tid < 132) a = softplusf_(v);   // read strengths
        else if (tid < 164) a = tanhf(v);        // write key
        else if (tid < 165) a = softplusf_(v);   // write strength
        else if (tid < 197) a = sigmf_(v);       // erase
        else if (tid < 229) a = tanhf(v);        // write vec
        else if (tid < 233) a = sigmf_(v);       // free gates
        else if (tid < 235) a = sigmf_(v);       // alloc gate, write gate
        else                a = v;               // read modes (raw)
        xi[tid] = a;
    }
    __syncthreads();

    // -------- key norms + read-mode softmax --------
    if (tid < 4) {
        float s = EPSF;
        for (int w = 0; w < 32; w++) { float k = xi[tid * 32 + w]; s += k * k; }
        knorm[tid] = rsqrtf(s);
    } else if (tid == 4) {
        float s = EPSF;
        for (int w = 0; w < 32; w++) { float k = xi[132 + w]; s += k * k; }
        knorm[4] = rsqrtf(s);
    } else if (tid >= 8 && tid < 12) {
        int r = tid - 8;
        float m0 = xi[235 + 3 * r], m1 = xi[236 + 3 * r], m2 = xi[237 + 3 * r];
        float mx = fmaxf(m0, fmaxf(m1, m2));
        float e0 = expf(m0 - mx), e1 = expf(m1 - mx), e2 = expf(m2 - mx);
        float inv = 1.f / (e0 + e1 + e2);
        modes[r][0] = e0 * inv; modes[r][1] = e1 * inv; modes[r][2] = e2 * inv;
    }
    __syncthreads();
    if (tid < 128)      { int r = tid >> 5, w = tid & 31; rkn[r][w] = xi[r * 32 + w] * knorm[r]; }
    else if (tid < 160) { int w = tid - 128; wkn[w] = xi[132 + w] * knorm[4]; }

    // -------- retention psi, usage update --------
    if (tid < 64) {
        float psi = 1.f;
#pragma unroll
        for (int r = 0; r < 4; r++) psi *= (1.f - xi[229 + r] * wrs[r][tid]);
        float un = (us[tid] + wws[tid] - us[tid] * wws[tid]) * psi;
        us[tid] = un;
        su[tid] = un;
        sidx[tid] = tid;
    }
    __syncthreads();

    // -------- stable bitonic sort ascending on (u, idx) --------
    for (int k = 2; k <= 64; k <<= 1)
        for (int j = k >> 1; j > 0; j >>= 1) {
            if (tid < 64) {
                int ixj = tid ^ j;
                if (ixj > tid) {
                    float av = su[tid], bv = su[ixj];
                    int ai = sidx[tid], bi = sidx[ixj];
                    bool up = ((tid & k) == 0);
                    bool gt = (av > bv) || (av == bv && ai > bi);
                    if (gt == up) { su[tid] = bv; su[ixj] = av; sidx[tid] = bi; sidx[ixj] = ai; }
                }
            }
            __syncthreads();
        }

    // -------- allocation weights (serial cumprod by thread 0) + old M row norms --------
    if (tid == 0) {
        float cp = 1.f;
        for (int k = 0; k < 64; k++) { avec[sidx[k]] = (1.f - su[k]) * cp; cp *= su[k]; }
    }
    if (tid >= 64 && tid < 128) {
        int n = tid - 64;
        float s = EPSF;
        for (int w = 0; w < 32; w++) { float m = Ms[n][w]; s += m * m; }
        rnorm[n] = rsqrtf(s);
    }
    __syncthreads();

    // -------- content write weights (softmax over 64) --------
    float wstr = xi[164];
    if (tid < 64) {
        float d = 0.f;
        for (int w = 0; w < 32; w++) d += wkn[w] * Ms[tid][w];
        cw[tid] = d * rnorm[tid] * wstr;
    }
    __syncthreads();
    if (tid < 64) red[tid] = cw[tid];
    __syncthreads();
    if (tid < 32) {
        float x = fmaxf(red[tid], red[tid + 32]);
        for (int s = 16; s; s >>= 1) x = fmaxf(x, __shfl_xor_sync(0xffffffffu, x, s));
        if (tid == 0) red[0] = x;
    }
    __syncthreads();
    float cmx = red[0];
    __syncthreads();
    float ev = (tid < 64) ? expf(cw[tid] - cmx) : 0.f;
    if (tid < 64) red[tid] = ev;
    __syncthreads();
    if (tid < 32) {
        float x = red[tid] + red[tid + 32];
        for (int s = 16; s; s >>= 1) x += __shfl_xor_sync(0xffffffffu, x, s);
        if (tid == 0) red[0] = x;
    }
    __syncthreads();
    if (tid < 64) cw[tid] = ev / red[0];
    __syncthreads();

    // -------- write weights --------
    float ag = xi[233], wg = xi[234];
    if (tid < 64) wwn[tid] = wg * (ag * avec[tid] + (1.f - ag) * cw[tid]);
    __syncthreads();

    // sum(ww)
    if (tid < 64) red[tid] = wwn[tid];
    __syncthreads();
    if (tid < 32) {
        float x = red[tid] + red[tid + 32];
        for (int s = 16; s; s >>= 1) x += __shfl_xor_sync(0xffffffffu, x, s);
        if (tid == 0) sww_sh = x;
    }

    // -------- memory write + link matrix update --------
    for (int i = tid; i < 2048; i += 256) {
        int n = i >> 5, w = i & 31;
        float m = Ms[n][w];
        m = m * (1.f - wwn[n] * xi[165 + w]) + wwn[n] * xi[197 + w];
        Ms[n][w] = m;
        g_M[b * 2048 + i] = m;
    }
    for (int i = tid; i < 4096; i += 256) {
        int ii = i >> 6, jj = i & 63;
        float lv = (ii == jj) ? 0.f
                 : ((1.f - wwn[ii] - wwn[jj]) * Ls[ii][jj] + wwn[ii] * ps[jj]);
        Ls[ii][jj] = lv;
        g_L[b * 4096 + i] = lv;
    }
    __syncthreads();

    // precedence, state writes, NEW M row norms
    if (tid < 64) {
        float pn = (1.f - sww_sh) * ps[tid] + wwn[tid];
        ps[tid] = pn;
        g_p[b * 64 + tid] = pn;
        g_u[b * 64 + tid] = us[tid];
        g_ww[b * 64 + tid] = wwn[tid];
    }
    if (tid >= 64 && tid < 128) {
        int n = tid - 64;
        float s = EPSF;
        for (int w = 0; w < 32; w++) { float m = Ms[n][w]; s += m * m; }
        rnorm[n] = rsqrtf(s);
    }
    __syncthreads();

    // -------- content read weights (4 groups of 64, softmax per group) --------
    int rr = tid >> 6, nn = tid & 63;
    float pre;
    {
        float d = 0.f;
        for (int w = 0; w < 32; w++) d += rkn[rr][w] * Ms[nn][w];
        pre = d * rnorm[nn] * xi[128 + rr];
    }
    // group max via per-warp reduce (each warp = one half of a group)
    float x = pre;
    for (int s = 16; s; s >>= 1) x = fmaxf(x, __shfl_xor_sync(0xffffffffu, x, s));
    if ((tid & 31) == 0) red[tid >> 5] = x;
    __syncthreads();
    float gmx = fmaxf(red[rr * 2], red[rr * 2 + 1]);
    float e = expf(pre - gmx);
    __syncthreads();
    x = e;
    for (int s = 16; s; s >>= 1) x += __shfl_xor_sync(0xffffffffu, x, s);
    if ((tid & 31) == 0) red[tid >> 5] = x;
    __syncthreads();
    float crv = e / (red[rr * 2] + red[rr * 2 + 1]);

    // -------- forward/backward weights + read-weight mix --------
    {
        float fwv = 0.f, bwv = 0.f;
        const float* wrow = wrs[rr];
        for (int m = 0; m < 64; m++) {
            float wv = wrow[m];
            fwv += Ls[nn][m] * wv;
            bwv += Ls[m][nn] * wv;
        }
        wrtmp[rr][nn] = modes[rr][0] * bwv + modes[rr][1] * crv + modes[rr][2] * fwv;
    }
    __syncthreads();

    g_wr[b * 256 + tid] = wrtmp[tid >> 6][tid & 63];
    if (tid < 128) {
        int r = tid >> 5, w = tid & 31;
        float s = 0.f;
        for (int n = 0; n < 64; n++) s += wrtmp[r][n] * Ms[n][w];
        g_rv[b * (RRD * WWD) + r * 32 + w] = s;
    }
}

// ---------------- launch ----------------
extern "C" void kernel_launch(void* const* d_in, const int* in_sizes, int n_in,
                              void* d_out, int out_size) {
    (void)in_sizes; (void)n_in; (void)out_size;
    const float* x     = (const float*)d_in[0];
    const float* Wih_e = (const float*)d_in[1];
    const float* Whh_e = (const float*)d_in[2];
    const float* b_e   = (const float*)d_in[3];
    const float* Wih_c = (const float*)d_in[4];
    const float* Whh_c = (const float*)d_in[5];
    const float* b_c   = (const float*)d_in[6];
    float* out = (float*)d_out;

    init_states<<<1024, 256>>>();

    // Phase A: x @ Wih_e^T + b_e for all (t,b)
    gemm_phase<<<dim3(256, 32), 256>>>(x, Wih_e, b_e, 0);

    // Encoder recurrence
    for (int t = 0; t < TT; t++)
        enc_step<<<128, 256>>>(Whh_e, t);

    // Phase C: enc @ Wih_c[:, :512]^T + b_c for all (t,b)
    gemm_phase<<<dim3(256, 48), 256>>>(nullptr, Wih_c, b_c, 1);

    // DNC recurrence
    for (int t = 0; t < TT; t++) {
        ctrl_step<<<127, 256>>>(Whh_c, Wih_c, out, t);
        dnc_step<<<64, 256>>>(t);
    }
}

// round 5
// speedup vs baseline: 1.1184x; 1.1184x over previous
#include <cuda_runtime.h>
#include <cuda_bf16.h>
#include <math.h>
#include <stdint.h>

// ---------------- problem constants ----------------
#define TT 256
#define BBATCH 64
#define HH 512
#define RRD 4
#define WWD 32
#define NND 64
#define HC 759          // HID_C
#define G4C 3036        // 4*HID_C
#define G4E 2048        // 4*H
#define KCC 887         // HC + R*W
#define KPAD 896
#define EPSF 1e-6f

// ---------------- device scratch (no allocs allowed) ----------------
__device__ float g_XWe[(size_t)TT * BBATCH * G4E];   // x @ Wih_e^T + b_e
__device__ float g_EWc[(size_t)TT * BBATCH * G4C];   // enc @ Wih_c[:, :H]^T + b_c
__device__ float g_enc[(size_t)TT * BBATCH * HH];    // encoder outputs
__device__ float g_he[2][BBATCH * HH];
__device__ float g_hc[2][BBATCH * HC];
__device__ float g_M[BBATCH * NND * WWD];
__device__ float g_u[BBATCH * NND];
__device__ float g_p[BBATCH * NND];
__device__ float g_ww[BBATCH * NND];
__device__ float g_L[BBATCH * NND * NND];
__device__ float g_wr[BBATCH * RRD * NND];
__device__ float g_rv[BBATCH * RRD * WWD];
__device__ unsigned g_barE;
__device__ unsigned g_barC;

__device__ __forceinline__ float sigmf_(float x) { return 1.f / (1.f + expf(-x)); }
__device__ __forceinline__ float softplusf_(float x) { return fmaxf(x, 0.f) + log1pf(expf(-fabsf(x))); }

// software grid barrier: all blocks co-resident (grid <= #SMs)
__device__ __forceinline__ void gbar(unsigned* ctr, unsigned target) {
    __syncthreads();
    if (threadIdx.x == 0) {
        __threadfence();
        atomicAdd(ctr, 1u);
        while (*(volatile unsigned*)ctr < target) { __nanosleep(32); }
        __threadfence();
    }
    __syncthreads();
}

// ---------------- init: zero all recurrent state ----------------
__global__ void init_states() {
    int i = blockIdx.x * blockDim.x + threadIdx.x;
    if (i == 0) { g_barE = 0u; g_barC = 0u; }
    if (i < 2 * BBATCH * HH) ((float*)g_he)[i] = 0.f;
    if (i < 2 * BBATCH * HC) ((float*)g_hc)[i] = 0.f;
    if (i < BBATCH * NND * WWD) g_M[i] = 0.f;
    if (i < BBATCH * NND) { g_u[i] = 0.f; g_p[i] = 0.f; g_ww[i] = 0.f; }
    if (i < BBATCH * NND * NND) g_L[i] = 0.f;
    if (i < BBATCH * RRD * NND) g_wr[i] = 0.f;
    if (i < BBATCH * RRD * WWD) g_rv[i] = 0.f;
}

// ---------------- big input-projection GEMMs (unchanged) ----------------
__global__ __launch_bounds__(256) void gemm_phase(const float* __restrict__ Ain,
                                                  const float* __restrict__ Wt,
                                                  const float* __restrict__ bias,
                                                  int phase) {
    const int Ncols = phase ? G4C : G4E;
    const int ldw   = phase ? 640 : 512;
    float* C        = phase ? g_EWc : g_XWe;
    const float* A  = phase ? g_enc : Ain;

    __shared__ float As[16][65];
    __shared__ float Bs[16][65];

    int tid = threadIdx.x;
    int m0 = blockIdx.x * 64;
    int n0 = blockIdx.y * 64;
    int tn = tid & 15, tm = tid >> 4;

    float acc[4][4];
#pragma unroll
    for (int i = 0; i < 4; i++)
#pragma unroll
        for (int j = 0; j < 4; j++) acc[i][j] = 0.f;

    for (int k0 = 0; k0 < 512; k0 += 16) {
#pragma unroll
        for (int i = 0; i < 4; i++) {
            int idx = tid + 256 * i;
            int mm = idx >> 4, kk = idx & 15;
            int m = m0 + mm;
            const float* arow;
            if (phase) arow = A + (size_t)m * 512;
            else { int t = m >> 6, b = m & 63; arow = A + ((size_t)b * TT + t) * 512; }
            As[kk][mm] = arow[k0 + kk];
        }
#pragma unroll
        for (int i = 0; i < 4; i++) {
            int idx = tid + 256 * i;
            int nn = idx >> 4, kk = idx & 15;
            int n = n0 + nn;
            Bs[kk][nn] = (n < Ncols) ? Wt[(size_t)n * ldw + k0 + kk] : 0.f;
        }
        __syncthreads();
#pragma unroll
        for (int k = 0; k < 16; k++) {
            float a[4], bv[4];
#pragma unroll
            for (int i = 0; i < 4; i++) { a[i] = As[k][tm * 4 + i]; bv[i] = Bs[k][tn * 4 + i]; }
#pragma unroll
            for (int i = 0; i < 4; i++)
#pragma unroll
                for (int j = 0; j < 4; j++) acc[i][j] += a[i] * bv[j];
        }
        __syncthreads();
    }
#pragma unroll
    for (int i = 0; i < 4; i++) {
        int m = m0 + tm * 4 + i;
#pragma unroll
        for (int j = 0; j < 4; j++) {
            int n = n0 + tn * 4 + j;
            if (n < Ncols) C[(size_t)m * Ncols + n] = acc[i][j] + bias[n];
        }
    }
}

// ---------------- persistent encoder: all 256 steps in one kernel ----------------
// 128 blocks x 256 threads. Block owns j-chunk of 4 (16 gate rows). Weights
// cached in smem once; cell state lives in a register.
__global__ __launch_bounds__(256, 1) void enc_persist(const float* __restrict__ Whh_e) {
    __shared__ float Wc[16][512];
    __shared__ float hs[32][65];
    __shared__ float gs[16][65];

    int tid = threadIdx.x;
    int j0 = blockIdx.x * 4;

    // one-time weight cache load
    for (int i = tid; i < 16 * 512; i += 256) {
        int lr = i >> 9, k = i & 511;
        int gate = lr >> 2, jj = lr & 3;
        Wc[lr][k] = Whh_e[(size_t)(gate * HH + j0 + jj) * HH + k];
    }

    int bb = tid & 31;
    int ry = tid >> 5;
    int lr0 = ry * 2;

    int bidx = tid & 63, jj_e = tid >> 6;   // elementwise mapping (fixed across steps)
    float creg = 0.f;                       // cell state in register
    unsigned target = 0;
    __syncthreads();

    for (int t = 0; t < TT; t++) {
        int par = t & 1;
        const float* hin = g_he[par];
        float* hout = g_he[par ^ 1];

        float acc[2][2];
#pragma unroll
        for (int i = 0; i < 2; i++)
#pragma unroll
            for (int r = 0; r < 2; r++) {
                int lr = lr0 + r;
                int gate = lr >> 2, jj = lr & 3;
                int bx = bb + i * 32;
                acc[i][r] = g_XWe[((size_t)t * BBATCH + bx) * G4E + gate * HH + j0 + jj];
            }

        for (int k0 = 0; k0 < HH; k0 += 32) {
#pragma unroll
            for (int i = 0; i < 8; i++) {
                int idx = tid + 256 * i;
                int bl = idx >> 5, kk = idx & 31;
                hs[kk][bl] = hin[bl * HH + k0 + kk];
            }
            __syncthreads();
#pragma unroll
            for (int k = 0; k < 32; k++) {
                float h0 = hs[k][bb], h1 = hs[k][bb + 32];
                float w0 = Wc[lr0][k0 + k], w1 = Wc[lr0 + 1][k0 + k];
                acc[0][0] += h0 * w0; acc[0][1] += h0 * w1;
                acc[1][0] += h1 * w0; acc[1][1] += h1 * w1;
            }
            __syncthreads();
        }
#pragma unroll
        for (int i = 0; i < 2; i++)
#pragma unroll
            for (int r = 0; r < 2; r++) gs[lr0 + r][bb + 32 * i] = acc[i][r];
        __syncthreads();

        // elementwise LSTM cell, c kept in register
        {
            int j = j0 + jj_e;
            float gi = gs[jj_e][bidx], gf = gs[4 + jj_e][bidx];
            float gg = gs[8 + jj_e][bidx], go = gs[12 + jj_e][bidx];
            float cn = sigmf_(gf) * creg + sigmf_(gi) * tanhf(gg);
            creg = cn;
            float hn = sigmf_(go) * tanhf(cn);
            hout[bidx * HH + j] = hn;
            g_enc[((size_t)t * BBATCH + bidx) * HH + j] = hn;
        }

        target += gridDim.x;
        gbar(&g_barE, target);
    }
}

// ---------------- persistent controller + fused DNC ----------------
// 127 blocks x 256 threads. Block owns j-chunk of 6 (24 gate rows), weights
// (Whh_c slice + Wih_c rv columns) cached in dynamic smem once. Blocks 0..63
// also run the DNC memory step for their batch between two grid barriers.
#define OFF_WC    0
#define OFF_HS    21504
#define OFF_GS    23584
#define OFF_LS    25144
#define OFF_MS    29304
#define OFF_XI    31416
#define OFF_WRS   31672
#define OFF_WRT   31928
#define OFF_US    32184
#define OFF_PS    32248
#define OFF_WWS   32312
#define OFF_AVEC  32376
#define OFF_CW    32440
#define OFF_WWN   32504
#define OFF_SU    32568
#define OFF_RNORM 32632
#define OFF_SIDX  32696
#define OFF_RKN   32760
#define OFF_WKN   32888
#define OFF_MODES 32920
#define OFF_RED   32936
#define OFF_KNORM 33000
#define OFF_SWW   33008
#define SMEM_CTRL_FLOATS 33016
#define SMEM_CTRL_BYTES  (SMEM_CTRL_FLOATS * 4)

__global__ __launch_bounds__(256, 1) void ctrl_persist(const float* __restrict__ Whh_c,
                                                       const float* __restrict__ Wih_c,
                                                       float* __restrict__ out) {
    extern __shared__ float dyn[];
    float* Wc = dyn + OFF_WC;     // [24][896]
    float* hs = dyn + OFF_HS;     // [32][65]
    float* gs = dyn + OFF_GS;     // [24][65]

    int tid = threadIdx.x;
    int j0 = blockIdx.x * 6;

    // one-time weight cache load (zero-padded beyond HC rows / KCC cols)
    for (int i = tid; i < 24 * KPAD; i += 256) {
        int lr = i / KPAD, k = i % KPAD;
        int gate = lr / 6, jj = lr % 6;
        int j = j0 + jj;
        float v = 0.f;
        if (j < HC && k < KCC) {
            int grow = gate * HC + j;
            v = (k < HH + 247) ? 0.f : 0.f;  // placeholder (overwritten below)
            v = (k < HC) ? Whh_c[(size_t)grow * HC + k]
                         : Wih_c[(size_t)grow * 640 + 512 + (k - HC)];
        }
        Wc[lr * KPAD + k] = v;
    }

    int bb = tid & 31;
    int ry = tid >> 5;
    int lr0 = ry * 3;

    float creg0 = 0.f, creg1 = 0.f;   // cell state in registers (e=tid, e=tid+256)
    unsigned target = 0;
    __syncthreads();

    for (int t = 0; t < TT; t++) {
        int par = t & 1;
        const float* hin = g_hc[par];
        float* hout = g_hc[par ^ 1];

        float acc[2][3];
#pragma unroll
        for (int i = 0; i < 2; i++)
#pragma unroll
            for (int r = 0; r < 3; r++) {
                int lr = lr0 + r;
                int gate = lr / 6, jj = lr % 6;
                int j = j0 + jj;
                int bx = bb + i * 32;
                acc[i][r] = (j < HC) ? g_EWc[((size_t)t * BBATCH + bx) * G4C + gate * HC + j] : 0.f;
            }

        for (int k0 = 0; k0 < KCC; k0 += 32) {
#pragma unroll
            for (int i = 0; i < 8; i++) {
                int idx = tid + 256 * i;
                int bl = idx >> 5, kk = idx & 31;
                int k = k0 + kk;
                float v = 0.f;
                if (k < HC) v = hin[bl * HC + k];
                else if (k < KCC) v = g_rv[bl * (RRD * WWD) + (k - HC)];
                hs[kk * 65 + bl] = v;
            }
            __syncthreads();
#pragma unroll
            for (int k = 0; k < 32; k++) {
                float h0 = hs[k * 65 + bb], h1 = hs[k * 65 + bb + 32];
#pragma unroll
                for (int r = 0; r < 3; r++) {
                    float w = Wc[(lr0 + r) * KPAD + k0 + k];
                    acc[0][r] += h0 * w;
                    acc[1][r] += h1 * w;
                }
            }
            __syncthreads();
        }
#pragma unroll
        for (int i = 0; i < 2; i++)
#pragma unroll
            for (int r = 0; r < 3; r++) gs[(lr0 + r) * 65 + bb + 32 * i] = acc[i][r];
        __syncthreads();

        // elementwise: 64 b x 6 j = 384 elems, cell state in registers
        {
            int e = tid;
            int bx = e & 63, jj = e >> 6;
            int j = j0 + jj;
            if (j < HC) {
                float gi = gs[jj * 65 + bx], gf = gs[(6 + jj) * 65 + bx];
                float gg = gs[(12 + jj) * 65 + bx], go = gs[(18 + jj) * 65 + bx];
                float cn = sigmf_(gf) * creg0 + sigmf_(gi) * tanhf(gg);
                creg0 = cn;
                float hn = sigmf_(go) * tanhf(cn);
                hout[bx * HC + j] = hn;
                if (j < HH) out[((size_t)bx * TT + t) * HH + j] = hn;
            }
            e = tid + 256;
            if (e < 384) {
                bx = e & 63; jj = e >> 6;
                j = j0 + jj;
                if (j < HC) {
                    float gi = gs[jj * 65 + bx], gf = gs[(6 + jj) * 65 + bx];
                    float gg = gs[(12 + jj) * 65 + bx], go = gs[(18 + jj) * 65 + bx];
                    float cn = sigmf_(gf) * creg1 + sigmf_(gi) * tanhf(gg);
                    creg1 = cn;
                    float hn = sigmf_(go) * tanhf(cn);
                    hout[bx * HC + j] = hn;
                    if (j < HH) out[((size_t)bx * TT + t) * HH + j] = hn;
                }
            }
        }

        target += gridDim.x;
        gbar(&g_barC, target);            // h fully written & visible

        // -------- fused DNC memory step (blocks 0..63, one per batch) --------
        if (blockIdx.x < 64) {
            int b = blockIdx.x;
            const float* h = g_hc[par ^ 1] + b * HC;
            float* Ls    = dyn + OFF_LS;      // [64][65]
            float* Ms    = dyn + OFF_MS;      // [64][33]
            float* xi    = dyn + OFF_XI;
            float* wrs   = dyn + OFF_WRS;     // [4][64]
            float* wrtmp = dyn + OFF_WRT;     // [4][64]
            float* us    = dyn + OFF_US;
            float* ps    = dyn + OFF_PS;
            float* wws   = dyn + OFF_WWS;
            float* avec  = dyn + OFF_AVEC;
            float* cwv   = dyn + OFF_CW;
            float* wwn   = dyn + OFF_WWN;
            float* su    = dyn + OFF_SU;
            float* rnorm = dyn + OFF_RNORM;
            int*   sidx  = (int*)(dyn + OFF_SIDX);
            float* rkn   = dyn + OFF_RKN;     // [4][32]
            float* wkn   = dyn + OFF_WKN;
            float* modes = dyn + OFF_MODES;   // [4][4] (stride 4)
            float* red   = dyn + OFF_RED;
            float* knorm = dyn + OFF_KNORM;
            float* sww   = dyn + OFF_SWW;

            for (int i = tid; i < 4096; i += 256) Ls[(i >> 6) * 65 + (i & 63)] = g_L[b * 4096 + i];
            for (int i = tid; i < 2048; i += 256) Ms[(i >> 5) * 33 + (i & 31)] = g_M[b * 2048 + i];
            wrs[tid] = g_wr[b * 256 + tid];
            if (tid < 64) { us[tid] = g_u[b * 64 + tid]; ps[tid] = g_p[b * 64 + tid]; wws[tid] = g_ww[b * 64 + tid]; }
            if (tid < 247) {
                float v = h[HH + tid];
                float a;
                if (tid < 128)      a = tanhf(v);
                else if (tid < 132) a = softplusf_(v);
                else if (tid < 164) a = tanhf(v);
                else if (tid < 165) a = softplusf_(v);
                else if (tid < 197) a = sigmf_(v);
                else if (tid < 229) a = tanhf(v);
                else if (tid < 235) a = sigmf_(v);
                else                a = v;
                xi[tid] = a;
            }
            __syncthreads();

            if (tid < 4) {
                float s = EPSF;
                for (int w = 0; w < 32; w++) { float k = xi[tid * 32 + w]; s += k * k; }
                knorm[tid] = rsqrtf(s);
            } else if (tid == 4) {
                float s = EPSF;
                for (int w = 0; w < 32; w++) { float k = xi[132 + w]; s += k * k; }
                knorm[4] = rsqrtf(s);
            } else if (tid >= 8 && tid < 12) {
                int r = tid - 8;
                float m0 = xi[235 + 3 * r], m1 = xi[236 + 3 * r], m2 = xi[237 + 3 * r];
                float mx = fmaxf(m0, fmaxf(m1, m2));
                float e0 = expf(m0 - mx), e1 = expf(m1 - mx), e2 = expf(m2 - mx);
                float inv = 1.f / (e0 + e1 + e2);
                modes[r * 4 + 0] = e0 * inv; modes[r * 4 + 1] = e1 * inv; modes[r * 4 + 2] = e2 * inv;
            }
            __syncthreads();
            if (tid < 128)      { int r = tid >> 5, w = tid & 31; rkn[r * 32 + w] = xi[r * 32 + w] * knorm[r]; }
            else if (tid < 160) { int w = tid - 128; wkn[w] = xi[132 + w] * knorm[4]; }

            if (tid < 64) {
                float psi = 1.f;
#pragma unroll
                for (int r = 0; r < 4; r++) psi *= (1.f - xi[229 + r] * wrs[r * 64 + tid]);
                float un = (us[tid] + wws[tid] - us[tid] * wws[tid]) * psi;
                us[tid] = un; su[tid] = un; sidx[tid] = tid;
            }
            __syncthreads();

            for (int k = 2; k <= 64; k <<= 1)
                for (int j = k >> 1; j > 0; j >>= 1) {
                    if (tid < 64) {
                        int ixj = tid ^ j;
                        if (ixj > tid) {
                            float av = su[tid], bv = su[ixj];
                            int ai = sidx[tid], bi = sidx[ixj];
                            bool up = ((tid & k) == 0);
                            bool gt = (av > bv) || (av == bv && ai > bi);
                            if (gt == up) { su[tid] = bv; su[ixj] = av; sidx[tid] = bi; sidx[ixj] = ai; }
                        }
                    }
                    __syncthreads();
                }

            if (tid == 0) {
                float cp = 1.f;
                for (int k = 0; k < 64; k++) { avec[sidx[k]] = (1.f - su[k]) * cp; cp *= su[k]; }
            }
            if (tid >= 64 && tid < 128) {
                int n = tid - 64;
                float s = EPSF;
                for (int w = 0; w < 32; w++) { float m = Ms[n * 33 + w]; s += m * m; }
                rnorm[n] = rsqrtf(s);
            }
            __syncthreads();

            float wstr = xi[164];
            if (tid < 64) {
                float d = 0.f;
                for (int w = 0; w < 32; w++) d += wkn[w] * Ms[tid * 33 + w];
                cwv[tid] = d * rnorm[tid] * wstr;
            }
            __syncthreads();
            if (tid < 64) red[tid] = cwv[tid];
            __syncthreads();
            if (tid < 32) {
                float x = fmaxf(red[tid], red[tid + 32]);
                for (int s = 16; s; s >>= 1) x = fmaxf(x, __shfl_xor_sync(0xffffffffu, x, s));
                if (tid == 0) red[0] = x;
            }
            __syncthreads();
            float cmx = red[0];
            __syncthreads();
            float ev = (tid < 64) ? expf(cwv[tid] - cmx) : 0.f;
            if (tid < 64) red[tid] = ev;
            __syncthreads();
            if (tid < 32) {
                float x = red[tid] + red[tid + 32];
                for (int s = 16; s; s >>= 1) x += __shfl_xor_sync(0xffffffffu, x, s);
                if (tid == 0) red[0] = x;
            }
            __syncthreads();
            if (tid < 64) cwv[tid] = ev / red[0];
            __syncthreads();

            float ag = xi[233], wg = xi[234];
            if (tid < 64) wwn[tid] = wg * (ag * avec[tid] + (1.f - ag) * cwv[tid]);
            __syncthreads();

            if (tid < 64) red[tid] = wwn[tid];
            __syncthreads();
            if (tid < 32) {
                float x = red[tid] + red[tid + 32];
                for (int s = 16; s; s >>= 1) x += __shfl_xor_sync(0xffffffffu, x, s);
                if (tid == 0) sww[0] = x;
            }

            for (int i = tid; i < 2048; i += 256) {
                int n = i >> 5, w = i & 31;
                float m = Ms[n * 33 + w];
                m = m * (1.f - wwn[n] * xi[165 + w]) + wwn[n] * xi[197 + w];
                Ms[n * 33 + w] = m;
                g_M[b * 2048 + i] = m;
            }
            for (int i = tid; i < 4096; i += 256) {
                int ii = i >> 6, jj = i & 63;
                float lv = (ii == jj) ? 0.f
                         : ((1.f - wwn[ii] - wwn[jj]) * Ls[ii * 65 + jj] + wwn[ii] * ps[jj]);
                Ls[ii * 65 + jj] = lv;
                g_L[b * 4096 + i] = lv;
            }
            __syncthreads();

            if (tid < 64) {
                float pn = (1.f - sww[0]) * ps[tid] + wwn[tid];
                ps[tid] = pn;
                g_p[b * 64 + tid] = pn;
                g_u[b * 64 + tid] = us[tid];
                g_ww[b * 64 + tid] = wwn[tid];
            }
            if (tid >= 64 && tid < 128) {
                int n = tid - 64;
                float s = EPSF;
                for (int w = 0; w < 32; w++) { float m = Ms[n * 33 + w]; s += m * m; }
                rnorm[n] = rsqrtf(s);
            }
            __syncthreads();

            int rr = tid >> 6, nn = tid & 63;
            float pre;
            {
                float d = 0.f;
                for (int w = 0; w < 32; w++) d += rkn[rr * 32 + w] * Ms[nn * 33 + w];
                pre = d * rnorm[nn] * xi[128 + rr];
            }
            float x = pre;
            for (int s = 16; s; s >>= 1) x = fmaxf(x, __shfl_xor_sync(0xffffffffu, x, s));
            if ((tid & 31) == 0) red[tid >> 5] = x;
            __syncthreads();
            float gmx = fmaxf(red[rr * 2], red[rr * 2 + 1]);
            float e = expf(pre - gmx);
            __syncthreads();
            x = e;
            for (int s = 16; s; s >>= 1) x += __shfl_xor_sync(0xffffffffu, x, s);
            if ((tid & 31) == 0) red[tid >> 5] = x;
            __syncthreads();
            float crv = e / (red[rr * 2] + red[rr * 2 + 1]);

            {
                float fwv = 0.f, bwv = 0.f;
                const float* wrow = wrs + rr * 64;
                for (int m = 0; m < 64; m++) {
                    float wv = wrow[m];
                    fwv += Ls[nn * 65 + m] * wv;
                    bwv += Ls[m * 65 + nn] * wv;
                }
                wrtmp[rr * 64 + nn] = modes[rr * 4 + 0] * bwv + modes[rr * 4 + 1] * crv + modes[rr * 4 + 2] * fwv;
            }
            __syncthreads();

            g_wr[b * 256 + tid] = wrtmp[tid];
            if (tid < 128) {
                int r = tid >> 5, w = tid & 31;
                float s = 0.f;
                for (int n = 0; n < 64; n++) s += wrtmp[r * 64 + n] * Ms[n * 33 + w];
                g_rv[b * (RRD * WWD) + r * 32 + w] = s;
            }
        }

        target += gridDim.x;
        gbar(&g_barC, target);            // rv / DNC state visible to all
    }
}

// ---------------- launch ----------------
extern "C" void kernel_launch(void* const* d_in, const int* in_sizes, int n_in,
                              void* d_out, int out_size) {
    (void)in_sizes; (void)n_in; (void)out_size;
    const float* x     = (const float*)d_in[0];
    const float* Wih_e = (const float*)d_in[1];
    const float* Whh_e = (const float*)d_in[2];
    const float* b_e   = (const float*)d_in[3];
    const float* Wih_c = (const float*)d_in[4];
    const float* Whh_c = (const float*)d_in[5];
    const float* b_c   = (const float*)d_in[6];
    float* out = (float*)d_out;

    static int smem_set = 0;
    if (!smem_set) {
        cudaFuncSetAttribute(ctrl_persist, cudaFuncAttributeMaxDynamicSharedMemorySize,
                             SMEM_CTRL_BYTES);
        smem_set = 1;
    }

    init_states<<<1024, 256>>>();

    // Phase A: x @ Wih_e^T + b_e for all (t,b)
    gemm_phase<<<dim3(256, 32), 256>>>(x, Wih_e, b_e, 0);

    // Encoder recurrence — one persistent kernel
    enc_persist<<<128, 256>>>(Whh_e);

    // Phase C: enc @ Wih_c[:, :512]^T + b_c for all (t,b)
    gemm_phase<<<dim3(256, 48), 256>>>(nullptr, Wih_c, b_c, 1);

    // Controller + DNC recurrence — one persistent kernel
    ctrl_persist<<<127, 256, SMEM_CTRL_BYTES>>>(Whh_c, Wih_c, out);
}